// round 17
// baseline (speedup 1.0000x reference)
#include <cuda_runtime.h>
#include <cuda_bf16.h>

#define N_NODES 100000
#define N_EDGES 3200000
#define IN_CH 16
#define HIDDEN 128
#define OUT_CH 16
#define CAP 128                // bin capacity per node (deg ~ Binom, mean 32)

typedef unsigned long long u64;

// ---------------- scratch (no allocation allowed) ----------------
__device__ float  g_dinv[N_NODES];
__device__ float4 g_y[N_NODES * 4];        // layer-1 gather source (dinv-scaled x)
__device__ float4 g_y2[N_NODES * 4];       // layer-2 gather source (dinv-scaled h2)
__device__ u64    g_bin[(size_t)N_NODES * CAP];   // packed (w_bits<<32 | src)
__device__ int    g_cur[N_NODES];          // per-node fill cursor (== in-degree)
__device__ int    g_is32;                  // 1 if edge_index is int32

// dtype-flexible edge load
__device__ __forceinline__ void load_edge(const void *ei, int e, int &s, int &d) {
    if (g_is32) {
        const int *p = (const int *)ei;
        s = p[e];
        d = p[e + N_EDGES];
    } else {
        const long long *p = (const long long *)ei;
        s = (int)p[e];
        d = (int)p[e + N_EDGES];
    }
}

// bf16-split helpers
__device__ __forceinline__ void split2(float x, float y, unsigned &hi, unsigned &lo) {
    __nv_bfloat162 H, L;
    H.x = __float2bfloat16(x);
    H.y = __float2bfloat16(y);
    L.x = __float2bfloat16(x - __bfloat162float(H.x));
    L.y = __float2bfloat16(y - __bfloat162float(H.y));
    hi = *reinterpret_cast<unsigned *>(&H);
    lo = *reinterpret_cast<unsigned *>(&L);
}
__device__ __forceinline__ void mma4(float c[4], const unsigned a[4],
                                     unsigned b0, unsigned b1) {
    asm volatile(
        "mma.sync.aligned.m16n8k16.row.col.f32.bf16.bf16.f32 "
        "{%0,%1,%2,%3}, {%4,%5,%6,%7}, {%8,%9}, {%0,%1,%2,%3};"
        : "+f"(c[0]), "+f"(c[1]), "+f"(c[2]), "+f"(c[3])
        : "r"(a[0]), "r"(a[1]), "r"(a[2]), "r"(a[3]), "r"(b0), "r"(b1));
}

// pull-mode aggregation for ONE node by ONE warp (R10 form — proven best).
// ysrc selects the feature array (g_y for layer 1, g_y2 for layer 2).
// returns the node's z quad on sub==0 lanes (q = lane&3), garbage elsewhere.
__device__ __forceinline__ float4 warp_agg_node(const float4 *__restrict__ ysrc,
                                                int d, int lane) {
    int q = lane & 3, sub = lane >> 2;
    int n = min(g_cur[d], CAP);
    const u64 *row = g_bin + (size_t)d * CAP;

    float4 acc = make_float4(0.0f, 0.0f, 0.0f, 0.0f);
    if (sub == 0) acc = __ldg(&ysrc[d * 4 + q]);   // self-loop seed

    for (int it0 = sub; it0 < n; it0 += 32) {
        u64 p[4];
#pragma unroll
        for (int j = 0; j < 4; j++) {
            int it = it0 + j * 8;
            p[j] = (it < n) ? __ldg(row + it) : 0;
        }
#pragma unroll
        for (int j = 0; j < 4; j++) {
            if (it0 + j * 8 < n) {
                int s = (int)(unsigned)p[j];
                float wv = __uint_as_float((unsigned)(p[j] >> 32));
                float4 v = __ldg(&ysrc[s * 4 + q]);
                acc.x += wv * v.x;
                acc.y += wv * v.y;
                acc.z += wv * v.z;
                acc.w += wv * v.w;
            }
        }
    }
#pragma unroll
    for (int o = 4; o < 32; o <<= 1) {
        acc.x += __shfl_xor_sync(0xFFFFFFFFu, acc.x, o);
        acc.y += __shfl_xor_sync(0xFFFFFFFFu, acc.y, o);
        acc.z += __shfl_xor_sync(0xFFFFFFFFu, acc.z, o);
        acc.w += __shfl_xor_sync(0xFFFFFFFFu, acc.w, o);
    }
    return acc;
}

// ---------------- kernels ----------------

// cursors = 0; block 0 does dtype detection (sample 4096 odd 32-bit words:
// int64 buffer -> high halves all zero; int32 buffer -> indices, nonzero)
__global__ void k_init(const unsigned int *__restrict__ wbuf) {
    int i = blockIdx.x * blockDim.x + threadIdx.x;
    if (i < N_NODES) g_cur[i] = 0;
    if (blockIdx.x == 0) {
        if (threadIdx.x == 0) g_is32 = 0;
        __syncthreads();
        unsigned v = 0;
        for (int k = threadIdx.x; k < 4096; k += 256) v |= wbuf[2 * k + 1];
        v = __reduce_or_sync(0xFFFFFFFFu, v);
        if ((threadIdx.x & 31) == 0 && v) atomicOr(&g_is32, 1);
    }
}

// scatter edges into per-dst bins (R10 single-edge form — best measured)
__global__ void k_scatter(const void *__restrict__ ei, const float *__restrict__ w) {
    int e = blockIdx.x * blockDim.x + threadIdx.x;
    if (e >= N_EDGES) return;
    int s, d;
    load_edge(ei, e, s, d);
    if ((unsigned)s >= N_NODES || (unsigned)d >= N_NODES) return;
    int pos = atomicAdd(&g_cur[d], 1);
    if (pos < CAP) {
        u64 p = ((u64)__float_as_uint(w[e]) << 32) | (unsigned)s;
        g_bin[(size_t)d * CAP + pos] = p;
    }
}

// warp per node: deg = 1 + sum(w over bin row); dinv = rsqrt(deg); y = x*dinv
__global__ void k_dinv_y(const float *__restrict__ x) {
    int warp = (blockIdx.x * blockDim.x + threadIdx.x) >> 5;
    int lane = threadIdx.x & 31;
    if (warp >= N_NODES) return;
    int d = warp;
    int n = min(g_cur[d], CAP);
    const u64 *row = g_bin + (size_t)d * CAP;
    float sum = 0.0f;
    for (int i = lane; i < n; i += 32)
        sum += __uint_as_float((unsigned)(__ldg(row + i) >> 32));
#pragma unroll
    for (int o = 16; o; o >>= 1) sum += __shfl_xor_sync(0xFFFFFFFFu, sum, o);
    float deg = 1.0f + sum;
    float di = (deg > 0.0f) ? rsqrtf(deg) : 0.0f;
    if (lane == 0) g_dinv[d] = di;
    if (lane < 4) {
        float4 v = ((const float4 *)x)[d * 4 + lane];
        v.x *= di; v.y *= di; v.z *= di; v.w *= di;
        g_y[d * 4 + lane] = v;
    }
}

// FUSED layer-1 aggregation + MLP. Block = 512 threads = 16 warps = 16 nodes.
// Each warp aggregates its node's z (from g_y) into SMEM; then warp 0 runs
// the 16-node bf16-split MMA tile and writes y2 = dinv*h2 to g_y2 (NOT g_y —
// other blocks may still be reading g_y; separate buffer avoids the race).
__global__ void __launch_bounds__(512) k_agg_mlp(const float *__restrict__ W1,
                                                 const float *__restrict__ b1,
                                                 const float *__restrict__ W2) {
    __shared__ uint4 fB1[16][32];       // [n-block][lane] : .xy=hi .zw=lo
    __shared__ uint4 fB2[16][32];       // [kb*2 + nb2][lane]
    __shared__ float sb1[HIDDEN];
    __shared__ float sz[16][16];        // z rows for the block's 16 nodes

    int t = threadIdx.x;
    int wid = t >> 5, lane = t & 31;
    int base = blockIdx.x * 16;

    // weight-fragment prep (all 512 threads, 1 fragment each per table)
    {
        int idx = t;                               // 0..511 : fB1
        int nb = idx >> 5, l = idx & 31;
        int g = l >> 2, m = l & 3;
        int n = nb * 8 + g;
        int k0 = 2 * m;
        uint4 f;
        unsigned hi, lo;
        split2(W1[(k0 + 0) * HIDDEN + n], W1[(k0 + 1) * HIDDEN + n], hi, lo);
        f.x = hi; f.z = lo;
        split2(W1[(k0 + 8) * HIDDEN + n], W1[(k0 + 9) * HIDDEN + n], hi, lo);
        f.y = hi; f.w = lo;
        fB1[nb][l] = f;

        int kb = idx >> 6, nb2 = (idx >> 5) & 1;   // 0..511 : fB2
        n = nb2 * 8 + g;
        k0 = kb * 16 + 2 * m;
        split2(W2[(k0 + 0) * OUT_CH + n], W2[(k0 + 1) * OUT_CH + n], hi, lo);
        f.x = hi; f.z = lo;
        split2(W2[(k0 + 8) * OUT_CH + n], W2[(k0 + 9) * OUT_CH + n], hi, lo);
        f.y = hi; f.w = lo;
        fB2[kb * 2 + nb2][l] = f;
    }
    if (t < HIDDEN) sb1[t] = b1[t];

    // ---- phase 1: each warp aggregates one node (reads g_y only) ----
    {
        float4 acc = warp_agg_node(g_y, base + wid, lane);
        if ((lane >> 2) == 0) {                    // lanes 0..3 hold quads 0..3
            int q = lane & 3;
            sz[wid][q * 4 + 0] = acc.x;
            sz[wid][q * 4 + 1] = acc.y;
            sz[wid][q * 4 + 2] = acc.z;
            sz[wid][q * 4 + 3] = acc.w;
        }
    }
    __syncthreads();

    // ---- phase 2: warp 0 runs the 16-node MMA tile ----
    if (wid != 0) return;
    int g = lane >> 2, m = lane & 3;
    int r0 = base + g, r1 = base + g + 8;
    float di0 = g_dinv[r0], di1 = g_dinv[r1];

    float2 v0 = *(const float2 *)&sz[g][2 * m];
    float2 v1 = *(const float2 *)&sz[g + 8][2 * m];
    float2 v2 = *(const float2 *)&sz[g][2 * m + 8];
    float2 v3 = *(const float2 *)&sz[g + 8][2 * m + 8];
    unsigned ahi[4], alo[4];
    split2(v0.x * di0, v0.y * di0, ahi[0], alo[0]);
    split2(v1.x * di1, v1.y * di1, ahi[1], alo[1]);
    split2(v2.x * di0, v2.y * di0, ahi[2], alo[2]);
    split2(v3.x * di1, v3.y * di1, ahi[3], alo[3]);

    float d2[2][4] = {{0, 0, 0, 0}, {0, 0, 0, 0}};

#pragma unroll
    for (int kb = 0; kb < 8; kb++) {
        float c[2][4] = {{0, 0, 0, 0}, {0, 0, 0, 0}};
#pragma unroll
        for (int p = 0; p < 2; p++) {
            uint4 f = fB1[2 * kb + p][lane];
            mma4(c[p], ahi, f.x, f.y);   // Ahi*Bhi
            mma4(c[p], alo, f.x, f.y);   // Alo*Bhi
            mma4(c[p], ahi, f.z, f.w);   // Ahi*Blo
        }
#pragma unroll
        for (int p = 0; p < 2; p++) {
            float bn0 = sb1[(2 * kb + p) * 8 + 2 * m];
            float bn1 = sb1[(2 * kb + p) * 8 + 2 * m + 1];
            c[p][0] = fmaxf(c[p][0] + bn0, 0.0f);
            c[p][1] = fmaxf(c[p][1] + bn1, 0.0f);
            c[p][2] = fmaxf(c[p][2] + bn0, 0.0f);
            c[p][3] = fmaxf(c[p][3] + bn1, 0.0f);
        }
        unsigned thi[4], tlo[4];
        split2(c[0][0], c[0][1], thi[0], tlo[0]);
        split2(c[0][2], c[0][3], thi[1], tlo[1]);
        split2(c[1][0], c[1][1], thi[2], tlo[2]);
        split2(c[1][2], c[1][3], thi[3], tlo[3]);
#pragma unroll
        for (int q = 0; q < 2; q++) {
            uint4 f = fB2[kb * 2 + q][lane];
            mma4(d2[q], thi, f.x, f.y);
            mma4(d2[q], tlo, f.x, f.y);
            mma4(d2[q], thi, f.z, f.w);
        }
    }

    // y2 = dinv * h2 -> g_y2 (separate buffer: no race with phase-1 readers)
    float *yf = (float *)g_y2;
    *(float2 *)(yf + (size_t)r0 * 16 + 2 * m)     = make_float2(d2[0][0] * di0, d2[0][1] * di0);
    *(float2 *)(yf + (size_t)r1 * 16 + 2 * m)     = make_float2(d2[0][2] * di1, d2[0][3] * di1);
    *(float2 *)(yf + (size_t)r0 * 16 + 8 + 2 * m) = make_float2(d2[1][0] * di0, d2[1][1] * di0);
    *(float2 *)(yf + (size_t)r1 * 16 + 8 + 2 * m) = make_float2(d2[1][2] * di1, d2[1][3] * di1);
}

// layer-2 aggregation (from g_y2) with fused epilogue: out = dinv*z + b2
__global__ void k_agg_final(const float *__restrict__ b2, float4 *__restrict__ out) {
    int warp = (blockIdx.x * blockDim.x + threadIdx.x) >> 5;
    int lane = threadIdx.x & 31;
    if (warp >= N_NODES) return;
    float4 acc = warp_agg_node(g_y2, warp, lane);
    if ((lane >> 2) == 0) {
        int q = lane & 3;
        float c = g_dinv[warp];
        float4 b = ((const float4 *)b2)[q];
        out[warp * 4 + q] = make_float4(b.x + c * acc.x, b.y + c * acc.y,
                                        b.z + c * acc.z, b.w + c * acc.w);
    }
}

// ---------------- launch ----------------
extern "C" void kernel_launch(void *const *d_in, const int *in_sizes, int n_in,
                              void *d_out, int out_size) {
    const float *x = 0, *w = 0, *W1 = 0, *b1 = 0, *W2 = 0, *b2 = 0;
    const void *ei = 0;
    for (int i = 0; i < n_in; i++) {
        switch (in_sizes[i]) {
            case N_NODES * IN_CH:  x = (const float *)d_in[i]; break;
            case 2 * N_EDGES:      ei = d_in[i]; break;
            case N_EDGES:          w = (const float *)d_in[i]; break;
            case IN_CH * HIDDEN:   if (!W1) W1 = (const float *)d_in[i];
                                   else     W2 = (const float *)d_in[i]; break;
            case HIDDEN:           b1 = (const float *)d_in[i]; break;
            case OUT_CH:           b2 = (const float *)d_in[i]; break;
        }
    }
    float4 *out = (float4 *)d_out;

    const int nbN  = (N_NODES + 255) / 256;
    const int nbE  = (N_EDGES + 255) / 256;
    const int nbWN = (N_NODES * 32 + 255) / 256;   // warp per node
    const int nbT  = (N_NODES + 15) / 16;          // 16 nodes per 512-thread block

    k_init<<<nbN, 256>>>((const unsigned int *)ei);
    k_scatter<<<nbE, 256>>>(ei, w);                // build bins (once)
    k_dinv_y<<<nbWN, 256>>>(x);                    // deg/dinv + y = x*dinv
    k_agg_mlp<<<nbT, 512>>>(W1, b1, W2);           // z (smem) -> y2 = dinv*MLP(dinv*z)
    k_agg_final<<<nbWN, 256>>>(b2, out);           // out = dinv*(y2+Σ) + b2
}